// round 1
// baseline (speedup 1.0000x reference)
#include <cuda_runtime.h>
#include <cuda_bf16.h>
#include <cstdint>

// GraphRec UV_Aggregator fused kernel (fp32, FFMA2 packed math).
// B=16384 nodes, L=50 history, D=64.
// One block (256 threads) handles NB=4 nodes = 200 rows, in 4 chunks of M=64 rows.
// Per chunk: gather x=[e_uv|e_r] (k-major smem) -> GEMM1(K=128) relu -> GEMM2(K=64) relu
// -> o stored; att-x=[o|uv_rep] -> ATT1(K=128) relu -> ATT2(K=64) relu -> dot att3 -> logit.
// Then per-node softmax over 50 logits + weighted sum of o.

#define NB 4
#define LHIST 50
#define ROWS (NB * LHIST)   // 200
#define NCHUNK 4            // ceil(200/64)
#define XSTRIDE 68          // padded row stride (floats) for k-major tiles (16B aligned, conflict-free)

// ---- smem layout (float offsets) ----
#define OFF_W1   0          // [128][64]
#define OFF_W2   8192       // [64][64]
#define OFF_A1   12288      // [128][64]
#define OFF_A2   20480      // [64][64]
#define OFF_A3   24576      // [64]
#define OFF_B1   24640      // [64]
#define OFF_B2   24704      // [64]
#define OFF_AB1  24768      // [64]
#define OFF_AB2  24832      // [64]
#define OFF_XT   24960      // [128][68] k-major activation tile
#define OFF_HT   33664      // [64][68]  k-major hidden tile
#define OFF_O    38016      // [200][64] o_history (row-major)
#define OFF_UV   50816      // [4][64]   uv_rep per node
#define OFF_LG   51072      // [200]     logits
#define SMEM_FLOATS 51272
#define SMEM_BYTES (SMEM_FLOATS * 4)

__device__ __forceinline__ unsigned long long dup2(float x) {
    unsigned long long r;
    unsigned u = __float_as_uint(x);
    asm("mov.b64 %0, {%1, %1};" : "=l"(r) : "r"(u));
    return r;
}

__device__ __forceinline__ void ffma2(unsigned long long& d, unsigned long long a, unsigned long long b) {
    asm("fma.rn.f32x2 %0, %1, %2, %0;" : "+l"(d) : "l"(a), "l"(b));
}

// C[64 x 64] tile: aT is k-major [K][XSTRIDE], bW row-major [K][64].
// Thread (rg, cg) computes rows rg*4..+3, cols cg*4..+3.
template <int K>
__device__ __forceinline__ void gemm_tile(const float* __restrict__ aT,
                                          const float* __restrict__ bW,
                                          float (&out)[4][4], int rg4, int cg4) {
    unsigned long long acc[4][2];
#pragma unroll
    for (int i = 0; i < 4; i++) { acc[i][0] = 0ull; acc[i][1] = 0ull; }
#pragma unroll 8
    for (int k = 0; k < K; k++) {
        float4 av = *reinterpret_cast<const float4*>(aT + k * XSTRIDE + rg4);
        ulonglong2 bv = *reinterpret_cast<const ulonglong2*>(bW + k * 64 + cg4);
        unsigned long long a0 = dup2(av.x), a1 = dup2(av.y), a2 = dup2(av.z), a3 = dup2(av.w);
        ffma2(acc[0][0], a0, bv.x); ffma2(acc[0][1], a0, bv.y);
        ffma2(acc[1][0], a1, bv.x); ffma2(acc[1][1], a1, bv.y);
        ffma2(acc[2][0], a2, bv.x); ffma2(acc[2][1], a2, bv.y);
        ffma2(acc[3][0], a3, bv.x); ffma2(acc[3][1], a3, bv.y);
    }
#pragma unroll
    for (int i = 0; i < 4; i++) {
        out[i][0] = __uint_as_float((unsigned)(acc[i][0] & 0xffffffffull));
        out[i][1] = __uint_as_float((unsigned)(acc[i][0] >> 32));
        out[i][2] = __uint_as_float((unsigned)(acc[i][1] & 0xffffffffull));
        out[i][3] = __uint_as_float((unsigned)(acc[i][1] >> 32));
    }
}

__device__ __forceinline__ void copyf4(float* dst, const float* __restrict__ src, int n4, int tid) {
    const float4* s = reinterpret_cast<const float4*>(src);
    float4* d = reinterpret_cast<float4*>(dst);
    for (int i = tid; i < n4; i += 256) d[i] = s[i];
}

__global__ __launch_bounds__(256, 1)
void uv_agg_kernel(const int* __restrict__ nodes,
                   const int* __restrict__ hist_uv,
                   const int* __restrict__ hist_r,
                   const float* __restrict__ v2e,
                   const float* __restrict__ u2e,
                   const float* __restrict__ r2e,
                   const float* __restrict__ w1, const float* __restrict__ b1,
                   const float* __restrict__ w2, const float* __restrict__ b2,
                   const float* __restrict__ a1w, const float* __restrict__ a1b,
                   const float* __restrict__ a2w, const float* __restrict__ a2b,
                   const float* __restrict__ a3w, const float* __restrict__ a3b,
                   float* __restrict__ out) {
    extern __shared__ float sm[];
    const int tid = threadIdx.x;
    const int b0 = blockIdx.x * NB;

    // ---- stage weights + biases ----
    copyf4(sm + OFF_W1, w1, 8192 / 4, tid);
    copyf4(sm + OFF_W2, w2, 4096 / 4, tid);
    copyf4(sm + OFF_A1, a1w, 8192 / 4, tid);
    copyf4(sm + OFF_A2, a2w, 4096 / 4, tid);
    copyf4(sm + OFF_A3, a3w, 16, tid);
    copyf4(sm + OFF_B1, b1, 16, tid);
    copyf4(sm + OFF_B2, b2, 16, tid);
    copyf4(sm + OFF_AB1, a1b, 16, tid);
    copyf4(sm + OFF_AB2, a2b, 16, tid);
    const float ab3 = a3b[0];

    // uv_rep gather: u2e_w[nodes[b]]
    {
        int n = tid >> 6, d = tid & 63;
        int nd = nodes[b0 + n];
        sm[OFF_UV + n * 64 + d] = u2e[(size_t)nd * 64 + d];
    }
    __syncthreads();

    const int rg = tid >> 4;        // 0..15  (rows rg*4..+3)
    const int cg = tid & 15;        // 0..15  (cols cg*4..+3)
    const int rg4 = rg * 4, cg4 = cg * 4;
    const int gr = tid & 63;        // gather row within chunk
    const int gq = tid >> 6;        // 0..3   gather quad-slot

    float* sXt = sm + OFF_XT;
    float* sHt = sm + OFF_HT;
    float* sO  = sm + OFF_O;
    float* sLg = sm + OFF_LG;

    for (int chunk = 0; chunk < NCHUNK; chunk++) {
        const int growg = chunk * 64 + gr;
        const bool gvalid = growg < ROWS;
        int nd = 0, l = 0, iu = 0, ir = 0;
        if (gvalid) {
            nd = growg / LHIST;
            l = growg - nd * LHIST;
            iu = hist_uv[(b0 + nd) * LHIST + l];
            ir = hist_r[(b0 + nd) * LHIST + l];
        }
        // ---- gather x = [e_uv | e_r] into k-major sXt ----
#pragma unroll
        for (int qi = 0; qi < 8; qi++) {
            int q = gq + qi * 4;            // 0..31
            int c = q * 4;                  // col base 0..124
            float4 v = make_float4(0.f, 0.f, 0.f, 0.f);
            if (gvalid) {
                v = (c < 64)
                    ? *reinterpret_cast<const float4*>(v2e + (size_t)iu * 64 + c)
                    : *reinterpret_cast<const float4*>(r2e + (size_t)ir * 64 + (c - 64));
            }
            sXt[(c + 0) * XSTRIDE + gr] = v.x;
            sXt[(c + 1) * XSTRIDE + gr] = v.y;
            sXt[(c + 2) * XSTRIDE + gr] = v.z;
            sXt[(c + 3) * XSTRIDE + gr] = v.w;
        }
        __syncthreads();

        float h[4][4];
        // ---- GEMM1: h = relu(x @ W1 + b1) ----
        gemm_tile<128>(sXt, sm + OFF_W1, h, rg4, cg4);
        {
            float4 bb = *reinterpret_cast<const float4*>(sm + OFF_B1 + cg4);
#pragma unroll
            for (int i = 0; i < 4; i++) {
                sHt[(cg4 + 0) * XSTRIDE + rg4 + i] = fmaxf(h[i][0] + bb.x, 0.f);
                sHt[(cg4 + 1) * XSTRIDE + rg4 + i] = fmaxf(h[i][1] + bb.y, 0.f);
                sHt[(cg4 + 2) * XSTRIDE + rg4 + i] = fmaxf(h[i][2] + bb.z, 0.f);
                sHt[(cg4 + 3) * XSTRIDE + rg4 + i] = fmaxf(h[i][3] + bb.w, 0.f);
            }
        }
        __syncthreads();

        // ---- GEMM2: o = relu(h @ W2 + b2) ----
        gemm_tile<64>(sHt, sm + OFF_W2, h, rg4, cg4);
        {
            float4 bb = *reinterpret_cast<const float4*>(sm + OFF_B2 + cg4);
#pragma unroll
            for (int i = 0; i < 4; i++) {
                float t0 = fmaxf(h[i][0] + bb.x, 0.f);
                float t1 = fmaxf(h[i][1] + bb.y, 0.f);
                float t2 = fmaxf(h[i][2] + bb.z, 0.f);
                float t3 = fmaxf(h[i][3] + bb.w, 0.f);
                // att-input part 1 (k-major)
                sXt[(cg4 + 0) * XSTRIDE + rg4 + i] = t0;
                sXt[(cg4 + 1) * XSTRIDE + rg4 + i] = t1;
                sXt[(cg4 + 2) * XSTRIDE + rg4 + i] = t2;
                sXt[(cg4 + 3) * XSTRIDE + rg4 + i] = t3;
                int grow = chunk * 64 + rg4 + i;
                if (grow < ROWS) {
                    *reinterpret_cast<float4*>(sO + grow * 64 + cg4) = make_float4(t0, t1, t2, t3);
                }
            }
        }
        // ---- fill att-input part 2: uv_rep[node(row)] ----
        {
            const float* uvp = sm + OFF_UV + nd * 64;
#pragma unroll
            for (int qi = 0; qi < 4; qi++) {
                int q = gq + qi * 4;       // 0..15
                int c = q * 4;
                float4 v = make_float4(0.f, 0.f, 0.f, 0.f);
                if (gvalid) v = *reinterpret_cast<const float4*>(uvp + c);
                sXt[(64 + c + 0) * XSTRIDE + gr] = v.x;
                sXt[(64 + c + 1) * XSTRIDE + gr] = v.y;
                sXt[(64 + c + 2) * XSTRIDE + gr] = v.z;
                sXt[(64 + c + 3) * XSTRIDE + gr] = v.w;
            }
        }
        __syncthreads();

        // ---- ATT1: a = relu([o|uv] @ A1 + ab1) ----
        gemm_tile<128>(sXt, sm + OFF_A1, h, rg4, cg4);
        {
            float4 bb = *reinterpret_cast<const float4*>(sm + OFF_AB1 + cg4);
#pragma unroll
            for (int i = 0; i < 4; i++) {
                sHt[(cg4 + 0) * XSTRIDE + rg4 + i] = fmaxf(h[i][0] + bb.x, 0.f);
                sHt[(cg4 + 1) * XSTRIDE + rg4 + i] = fmaxf(h[i][1] + bb.y, 0.f);
                sHt[(cg4 + 2) * XSTRIDE + rg4 + i] = fmaxf(h[i][2] + bb.z, 0.f);
                sHt[(cg4 + 3) * XSTRIDE + rg4 + i] = fmaxf(h[i][3] + bb.w, 0.f);
            }
        }
        __syncthreads();

        // ---- ATT2 + att3 dot -> logits ----
        gemm_tile<64>(sHt, sm + OFF_A2, h, rg4, cg4);
        {
            float4 bb = *reinterpret_cast<const float4*>(sm + OFF_AB2 + cg4);
            float4 w3 = *reinterpret_cast<const float4*>(sm + OFF_A3 + cg4);
            float p[4];
#pragma unroll
            for (int i = 0; i < 4; i++) {
                p[i] = fmaxf(h[i][0] + bb.x, 0.f) * w3.x
                     + fmaxf(h[i][1] + bb.y, 0.f) * w3.y
                     + fmaxf(h[i][2] + bb.z, 0.f) * w3.z
                     + fmaxf(h[i][3] + bb.w, 0.f) * w3.w;
            }
            // reduce across the 16 cg lanes (xor <16 stays within each half-warp = one rg)
#pragma unroll
            for (int off = 8; off >= 1; off >>= 1) {
#pragma unroll
                for (int i = 0; i < 4; i++)
                    p[i] += __shfl_xor_sync(0xffffffffu, p[i], off);
            }
            if (cg == 0) {
#pragma unroll
                for (int i = 0; i < 4; i++) {
                    int grow = chunk * 64 + rg4 + i;
                    if (grow < ROWS) sLg[grow] = p[i] + ab3;
                }
            }
        }
        __syncthreads();
    }

    // ---- per-node softmax over 50 + weighted sum of o ----
    {
        int n = tid >> 6, d = tid & 63;
        const float* lg = sLg + n * LHIST;
        float mx = -1e30f;
#pragma unroll 10
        for (int l = 0; l < LHIST; l++) mx = fmaxf(mx, lg[l]);
        float s = 0.f, acc = 0.f;
#pragma unroll 10
        for (int l = 0; l < LHIST; l++) {
            float e = __expf(lg[l] - mx);
            s += e;
            acc += e * sO[(n * LHIST + l) * 64 + d];
        }
        out[(size_t)(b0 + n) * 64 + d] = acc / s;
    }
}

extern "C" void kernel_launch(void* const* d_in, const int* in_sizes, int n_in,
                              void* d_out, int out_size) {
    const int*   nodes = (const int*)d_in[0];
    const int*   huv   = (const int*)d_in[1];
    const int*   hr    = (const int*)d_in[2];
    const float* v2e   = (const float*)d_in[3];
    const float* u2e   = (const float*)d_in[4];
    const float* r2e   = (const float*)d_in[5];
    const float* w1    = (const float*)d_in[6];
    const float* b1    = (const float*)d_in[7];
    const float* w2    = (const float*)d_in[8];
    const float* b2    = (const float*)d_in[9];
    const float* a1w   = (const float*)d_in[10];
    const float* a1b   = (const float*)d_in[11];
    const float* a2w   = (const float*)d_in[12];
    const float* a2b   = (const float*)d_in[13];
    const float* a3w   = (const float*)d_in[14];
    const float* a3b   = (const float*)d_in[15];
    float* out = (float*)d_out;

    cudaFuncSetAttribute(uv_agg_kernel, cudaFuncAttributeMaxDynamicSharedMemorySize, SMEM_BYTES);
    const int B = in_sizes[0];          // 16384
    uv_agg_kernel<<<B / NB, 256, SMEM_BYTES>>>(nodes, huv, hr, v2e, u2e, r2e,
                                               w1, b1, w2, b2, a1w, a1b, a2w, a2b, a3w, a3b, out);
}

// round 3
// speedup vs baseline: 2.3643x; 2.3643x over previous
#include <cuda_runtime.h>
#include <cstdint>

// ============================================================================
// GraphRec UV_Aggregator — legacy mma.sync tf32 (HMMA fallback) fused kernel.
// compute_103 PTX-compatible (NO tcgen05 — harness emits non-'a' PTX).
// Persistent 148 CTAs. Per group: NB=2 nodes = 100 rows -> one 128x64 tile
// through GEMM1(K=128)->GEMM2(K=64)->ATT1(K=128)->ATT2(K=64) in smem, then
// logits -> softmax(50) -> weighted sum.
// Storage layout: row-major, cols permuted within 8-groups so every mma
// fragment load/store pairs into 8B LDS.64. Strides ≡ 4 (mod 32) for uniform
// bank spread. Values stored pre-converted to tf32 bit patterns.
// ============================================================================

#define TPB   256
#define LHIST 50
#define NB    2
#define VROWS (NB * LHIST)   // 100
#define STRA  132            // stride (floats) for 128-k-col buffers
#define STRH  68             // stride for 64-k-col buffers

// ---- smem float offsets ----
#define O_A0   0             // 128 x STRA  (X / [o|uv] tile, tf32 bits)
#define O_A1   16896         // 128 x STRH  (H tile)
#define O_W1   25600         // 64 x STRA   (w_r1 staged, n-major)
#define O_A1W  34048         // 64 x STRA   (att1 staged)
#define O_W2   42496         // 64 x STRH   (w_r2 staged)
#define O_A2W  46848         // 64 x STRH   (att2 staged)
#define O_B1   51200
#define O_B2   51264
#define O_AB1  51328
#define O_AB2  51392
#define O_A3   51456
#define O_UV   51520         // 2 x 64 fp32
#define O_LGP  51648         // 2 x 128 logit partials
#define O_LG   51904         // 128 logits
#define SMEM_FLOATS 52032
#define SMEM_BYTES  (SMEM_FLOATS * 4)   // 208128

__device__ __forceinline__ int permc(int lc) { return 2 * (lc & 3) + (lc >> 2); }
__device__ __forceinline__ int scol(int c)   { return (c & ~7) + permc(c & 7); }

__device__ __forceinline__ float tf(float x) {
    uint32_t u;
    asm("cvt.rna.tf32.f32 %0, %1;" : "=r"(u) : "f"(x));
    return __uint_as_float(u);
}

__device__ __forceinline__ void mma8(float (&d)[4], uint32_t a0, uint32_t a1,
                                     uint32_t a2, uint32_t a3, uint32_t b0, uint32_t b1) {
    asm volatile(
        "mma.sync.aligned.m16n8k8.row.col.f32.tf32.tf32.f32 "
        "{%0,%1,%2,%3}, {%4,%5,%6,%7}, {%8,%9}, {%0,%1,%2,%3};"
        : "+f"(d[0]), "+f"(d[1]), "+f"(d[2]), "+f"(d[3])
        : "r"(a0), "r"(a1), "r"(a2), "r"(a3), "r"(b0), "r"(b1));
}

// GEMM: C[2 m-tiles][4 n-tiles] += A(rows 32wq..+31) @ B(cols 32wh..+31)^T
// A: [row][k-storage] stride SA; B: [n][k-storage] stride SB (both tf32 bits).
template <int KSTEPS, int SA, int SB>
__device__ __forceinline__ void gemm(const float* __restrict__ As,
                                     const float* __restrict__ Bs,
                                     float (&d)[2][4][4],
                                     int wq, int wh, int r, int m) {
    const float* pa0 = As + (wq * 32 + r) * SA + 2 * m;
    const float* pb0 = Bs + (wh * 32 + r) * SB + 2 * m;
#pragma unroll
    for (int g = 0; g < KSTEPS; g++) {
        uint2 aA = *(const uint2*)(pa0 + 8 * g);               // mt0: a0,a2
        uint2 aB = *(const uint2*)(pa0 + 8 * SA + 8 * g);      // mt0: a1,a3
        uint2 aC = *(const uint2*)(pa0 + 16 * SA + 8 * g);     // mt1: a0,a2
        uint2 aD = *(const uint2*)(pa0 + 24 * SA + 8 * g);     // mt1: a1,a3
        uint2 b0 = *(const uint2*)(pb0 + 8 * g);
        uint2 b1 = *(const uint2*)(pb0 + 8 * SB + 8 * g);
        uint2 b2 = *(const uint2*)(pb0 + 16 * SB + 8 * g);
        uint2 b3 = *(const uint2*)(pb0 + 24 * SB + 8 * g);
        mma8(d[0][0], aA.x, aB.x, aA.y, aB.y, b0.x, b0.y);
        mma8(d[0][1], aA.x, aB.x, aA.y, aB.y, b1.x, b1.y);
        mma8(d[0][2], aA.x, aB.x, aA.y, aB.y, b2.x, b2.y);
        mma8(d[0][3], aA.x, aB.x, aA.y, aB.y, b3.x, b3.y);
        mma8(d[1][0], aC.x, aD.x, aC.y, aD.y, b0.x, b0.y);
        mma8(d[1][1], aC.x, aD.x, aC.y, aD.y, b1.x, b1.y);
        mma8(d[1][2], aC.x, aD.x, aC.y, aD.y, b2.x, b2.y);
        mma8(d[1][3], aC.x, aD.x, aC.y, aD.y, b3.x, b3.y);
    }
}

__device__ __forceinline__ void zero_acc(float (&d)[2][4][4]) {
#pragma unroll
    for (int i = 0; i < 2; i++)
#pragma unroll
        for (int j = 0; j < 4; j++)
#pragma unroll
            for (int k = 0; k < 4; k++) d[i][j][k] = 0.f;
}

// Epilogue: relu(d + bias) -> tf32 bits into dst[row][scol], stride SD.
__device__ __forceinline__ void epi_store(float (&d)[2][4][4], const float* __restrict__ bias,
                                          float* __restrict__ dst, int SD,
                                          int wq, int wh, int r, int m) {
    const int s0loc = (m & 1) * 4 + (m >> 1);   // perm(2m)
#pragma unroll
    for (int mt = 0; mt < 2; mt++) {
        int row0 = wq * 32 + mt * 16 + r;
#pragma unroll
        for (int nt = 0; nt < 4; nt++) {
            int c0 = wh * 32 + nt * 8 + 2 * m;
            float bv0 = bias[c0], bv1 = bias[c0 + 1];
            int s0 = (wh * 4 + nt) * 8 + s0loc;
            dst[row0 * SD + s0]            = tf(fmaxf(d[mt][nt][0] + bv0, 0.f));
            dst[row0 * SD + s0 + 2]        = tf(fmaxf(d[mt][nt][1] + bv1, 0.f));
            dst[(row0 + 8) * SD + s0]      = tf(fmaxf(d[mt][nt][2] + bv0, 0.f));
            dst[(row0 + 8) * SD + s0 + 2]  = tf(fmaxf(d[mt][nt][3] + bv1, 0.f));
        }
    }
}

// stage weight W[K][64] (gmem, row-major) -> dst[n][k-storage] tf32 bits.
__device__ __forceinline__ void stage_w(float* __restrict__ dst, const float* __restrict__ W,
                                        int K, int strb, int tid) {
    for (int idx = tid; idx < K * 64; idx += TPB) {
        int k = idx >> 6, n = idx & 63;
        dst[n * strb + scol(k)] = tf(W[idx]);
    }
}

__global__ __launch_bounds__(TPB, 1)
void uv_agg_mma(const int* __restrict__ nodes,
                const int* __restrict__ hist_uv,
                const int* __restrict__ hist_r,
                const float* __restrict__ v2e,
                const float* __restrict__ u2e,
                const float* __restrict__ r2e,
                const float* __restrict__ w1, const float* __restrict__ b1,
                const float* __restrict__ w2, const float* __restrict__ b2,
                const float* __restrict__ a1w, const float* __restrict__ a1b,
                const float* __restrict__ a2w, const float* __restrict__ a2b,
                const float* __restrict__ a3w, const float* __restrict__ a3b,
                float* __restrict__ out, int ngroups) {
    extern __shared__ float smf[];
    const int tid = threadIdx.x;
    const int wid = tid >> 5, lane = tid & 31;
    const int wq = wid & 3;          // row quarter
    const int wh = wid >> 2;         // col half
    const int r = lane >> 2, m = lane & 3;

    // ---- stage weights + biases once per CTA ----
    stage_w(smf + O_W1, w1, 128, STRA, tid);
    stage_w(smf + O_A1W, a1w, 128, STRA, tid);
    stage_w(smf + O_W2, w2, 64, STRH, tid);
    stage_w(smf + O_A2W, a2w, 64, STRH, tid);
    if (tid < 64) {
        smf[O_B1 + tid]  = b1[tid];
        smf[O_B2 + tid]  = b2[tid];
        smf[O_AB1 + tid] = a1b[tid];
        smf[O_AB2 + tid] = a2b[tid];
        smf[O_A3 + tid]  = a3w[tid];
    }
    const float ab3v = a3b[0];
    __syncthreads();

    const int gr = tid >> 1, ghalf = tid & 1;   // gather: row, col-half

    for (int g = blockIdx.x; g < ngroups; g += gridDim.x) {
        const int b0 = g * NB;

        // ---- gather uv_rep + x = [e_uv | e_r] -> A0 (tf32, permuted) ----
        if (tid < 128) {
            int n = tid >> 6, d = tid & 63;
            smf[O_UV + n * 64 + d] = u2e[(size_t)nodes[b0 + n] * 64 + d];
        }
        if (gr < VROWS) {
            int n = gr >= LHIST;
            int l = gr - n * LHIST;
            int hidx = (b0 + n) * LHIST + l;
            const float* src = ghalf ? (r2e + (size_t)hist_r[hidx] * 64)
                                     : (v2e + (size_t)hist_uv[hidx] * 64);
            float* drow = smf + O_A0 + gr * STRA + ghalf * 64;
#pragma unroll
            for (int q = 0; q < 8; q++) {
                float4 v0 = *(const float4*)(src + q * 8);
                float4 v1 = *(const float4*)(src + q * 8 + 4);
                float2* d2 = (float2*)(drow + q * 8);
                d2[0] = make_float2(tf(v0.x), tf(v1.x));
                d2[1] = make_float2(tf(v0.y), tf(v1.y));
                d2[2] = make_float2(tf(v0.z), tf(v1.z));
                d2[3] = make_float2(tf(v0.w), tf(v1.w));
            }
        }
        __syncthreads();

        float d[2][4][4];

        // ==== GEMM1: H = relu(X @ W1 + b1) ====
        zero_acc(d);
        gemm<16, STRA, STRA>(smf + O_A0, smf + O_W1, d, wq, wh, r, m);
        __syncthreads();
        epi_store(d, smf + O_B1, smf + O_A1, STRH, wq, wh, r, m);
        // uv_rep -> A0 cols 64..127 (A0 fully consumed by GEMM1)
        if (gr < VROWS) {
            int n = gr >= LHIST;
            const float* uvp = smf + O_UV + n * 64;
            float* drow = smf + O_A0 + gr * STRA + 64;
#pragma unroll
            for (int qq = 0; qq < 4; qq++) {
                int q = ghalf * 4 + qq;
                float4 v0 = *(const float4*)(uvp + q * 8);
                float4 v1 = *(const float4*)(uvp + q * 8 + 4);
                float2* d2 = (float2*)(drow + q * 8);
                d2[0] = make_float2(tf(v0.x), tf(v1.x));
                d2[1] = make_float2(tf(v0.y), tf(v1.y));
                d2[2] = make_float2(tf(v0.z), tf(v1.z));
                d2[3] = make_float2(tf(v0.w), tf(v1.w));
            }
        }
        __syncthreads();

        // ==== GEMM2: o = relu(H @ W2 + b2) -> A0 cols 0..63 ====
        zero_acc(d);
        gemm<8, STRH, STRH>(smf + O_A1, smf + O_W2, d, wq, wh, r, m);
        epi_store(d, smf + O_B2, smf + O_A0, STRA, wq, wh, r, m);
        __syncthreads();

        // ==== GEMM3: H2 = relu([o|uv] @ A1w + ab1) ====
        zero_acc(d);
        gemm<16, STRA, STRA>(smf + O_A0, smf + O_A1W, d, wq, wh, r, m);
        epi_store(d, smf + O_AB1, smf + O_A1, STRH, wq, wh, r, m);
        __syncthreads();

        // ==== GEMM4: logits = relu(H2 @ A2w + ab2) . a3 ====
        zero_acc(d);
        gemm<8, STRH, STRH>(smf + O_A1, smf + O_A2W, d, wq, wh, r, m);
        {
            float p0[2] = {0.f, 0.f}, p1[2] = {0.f, 0.f};
#pragma unroll
            for (int mt = 0; mt < 2; mt++)
#pragma unroll
                for (int nt = 0; nt < 4; nt++) {
                    int c0 = wh * 32 + nt * 8 + 2 * m;
                    float w30 = smf[O_A3 + c0], w31 = smf[O_A3 + c0 + 1];
                    float bb0 = smf[O_AB2 + c0], bb1 = smf[O_AB2 + c0 + 1];
                    p0[mt] += fmaxf(d[mt][nt][0] + bb0, 0.f) * w30
                            + fmaxf(d[mt][nt][1] + bb1, 0.f) * w31;
                    p1[mt] += fmaxf(d[mt][nt][2] + bb0, 0.f) * w30
                            + fmaxf(d[mt][nt][3] + bb1, 0.f) * w31;
                }
#pragma unroll
            for (int off = 1; off <= 2; off <<= 1) {
#pragma unroll
                for (int mt = 0; mt < 2; mt++) {
                    p0[mt] += __shfl_xor_sync(0xffffffffu, p0[mt], off);
                    p1[mt] += __shfl_xor_sync(0xffffffffu, p1[mt], off);
                }
            }
            if (m == 0) {
#pragma unroll
                for (int mt = 0; mt < 2; mt++) {
                    int row = wq * 32 + mt * 16 + r;
                    smf[O_LGP + wh * 128 + row] = p0[mt];
                    smf[O_LGP + wh * 128 + row + 8] = p1[mt];
                }
            }
        }
        __syncthreads();
        if (tid < VROWS)
            smf[O_LG + tid] = smf[O_LGP + tid] + smf[O_LGP + 128 + tid] + ab3v;
        __syncthreads();

        // ---- softmax(50) + weighted sum of o (o read from A0, tf32 bits) ----
        if (tid < 128) {
            int n = tid >> 6, dcol = tid & 63;
            int sc = scol(dcol);
            const float* lg = smf + O_LG + n * LHIST;
            const float* ob = smf + O_A0 + n * LHIST * STRA + sc;
            float mx = -1e30f;
#pragma unroll 10
            for (int l = 0; l < LHIST; l++) mx = fmaxf(mx, lg[l]);
            float s = 0.f, acc = 0.f;
#pragma unroll 10
            for (int l = 0; l < LHIST; l++) {
                float e = __expf(lg[l] - mx);
                s += e;
                acc += e * ob[l * STRA];
            }
            out[(size_t)(b0 + n) * 64 + dcol] = acc / s;
        }
        __syncthreads();
    }
}

extern "C" void kernel_launch(void* const* d_in, const int* in_sizes, int n_in,
                              void* d_out, int out_size) {
    const int*   nodes = (const int*)d_in[0];
    const int*   huv   = (const int*)d_in[1];
    const int*   hr    = (const int*)d_in[2];
    const float* v2e   = (const float*)d_in[3];
    const float* u2e   = (const float*)d_in[4];
    const float* r2e   = (const float*)d_in[5];
    const float* w1    = (const float*)d_in[6];
    const float* b1    = (const float*)d_in[7];
    const float* w2    = (const float*)d_in[8];
    const float* b2    = (const float*)d_in[9];
    const float* a1w   = (const float*)d_in[10];
    const float* a1b   = (const float*)d_in[11];
    const float* a2w   = (const float*)d_in[12];
    const float* a2b   = (const float*)d_in[13];
    const float* a3w   = (const float*)d_in[14];
    const float* a3b   = (const float*)d_in[15];
    float* out = (float*)d_out;

    const int B = in_sizes[0];
    const int ngroups = B / NB;

    static int attr_set = 0;
    if (!attr_set) {
        cudaFuncSetAttribute(uv_agg_mma, cudaFuncAttributeMaxDynamicSharedMemorySize, SMEM_BYTES);
        attr_set = 1;
    }
    uv_agg_mma<<<148, TPB, SMEM_BYTES>>>(nodes, huv, hr, v2e, u2e, r2e,
                                         w1, b1, w2, b2, a1w, a1b, a2w, a2b,
                                         a3w, a3b, out, ngroups);
}

// round 4
// speedup vs baseline: 3.8592x; 1.6323x over previous
#include <cuda_runtime.h>
#include <cuda_fp16.h>
#include <cstdint>

// ============================================================================
// GraphRec UV_Aggregator — mma.sync m16n8k16 fp16 (fp32 accum) fused kernel.
// compute_103-safe (no tcgen05). Persistent 148 CTAs, 512 threads.
// Per group: NB=4 nodes = 200 rows -> one 256x64 tile through
// GEMM1(K=128)->GEMM2(K=64)->ATT1(K=128)->ATT2(K=64), logits, softmax(50),
// weighted sum. Operands fp16, pair-permuted k-layout so every fragment is one
// 8B LDS.64 (conflict-free). o kept in fp16 (GEMM3 operand) + fp32 (softmax).
// ============================================================================

#define TPB   512
#define NB    4
#define LHIST 50
#define VROWS 200
#define SA    136    // halves stride, 128-k buffers (272B; banks ≡16B mod128)
#define SH    72     // halves stride, 64-k buffers
#define SOF   68     // floats stride, o fp32

// ---- smem byte offsets ----
#define O_A0   0u        // 256 x SA halves : X / [o|uv]
#define O_H    69632u    // 256 x SH halves : hidden
#define O_W1   106496u   // 64 x SA halves
#define O_A1W  123904u
#define O_W2   141312u   // 64 x SH halves
#define O_A2W  150528u
#define O_OF   159744u   // 200 x SOF floats (o fp32)
#define O_B1   214144u
#define O_B2   214400u
#define O_AB1  214656u
#define O_AB2  214912u
#define O_A3   215168u
#define O_UV   215424u   // 4 x 64 floats
#define O_LGP  216448u   // 2 x 256 floats
#define O_LG   218496u   // 256 floats
#define SMEM_BYTES 219520u

__device__ __forceinline__ void mma16(float (&d)[4], uint32_t a0, uint32_t a1,
                                      uint32_t a2, uint32_t a3, uint32_t b0, uint32_t b1) {
    asm volatile(
        "mma.sync.aligned.m16n8k16.row.col.f32.f16.f16.f32 "
        "{%0,%1,%2,%3}, {%4,%5,%6,%7}, {%8,%9}, {%0,%1,%2,%3};"
        : "+f"(d[0]), "+f"(d[1]), "+f"(d[2]), "+f"(d[3])
        : "r"(a0), "r"(a1), "r"(a2), "r"(a3), "r"(b0), "r"(b1));
}

// pack two floats -> half2 bits
__device__ __forceinline__ uint32_t h2(float lo, float hi) {
    __half2 h = __floats2half2_rn(lo, hi);
    return *reinterpret_cast<uint32_t*>(&h);
}

// GEMM: C[2 m16-tiles][4 n8-tiles] += A(rows 32*wq..+31) @ B(cols 32*wh..+31)^T
// A: half [row][k-storage] stride SAs; B: half [n][k-storage] stride SBs.
template <int KST, int SAs, int SBs>
__device__ __forceinline__ void gemm(const __half* __restrict__ As,
                                     const __half* __restrict__ Bs,
                                     float (&d)[2][4][4],
                                     int wq, int wh, int r, int m) {
    const __half* pa = As + (wq * 32 + r) * SAs + m * 4;
    const __half* pb = Bs + (wh * 32 + r) * SBs + m * 4;
#pragma unroll
    for (int g = 0; g < KST; g++) {
        uint2 aA = *(const uint2*)(pa + 16 * g);               // rows R   : a0,a2
        uint2 aB = *(const uint2*)(pa + 8 * SAs + 16 * g);     // rows R+8 : a1,a3
        uint2 aC = *(const uint2*)(pa + 16 * SAs + 16 * g);
        uint2 aD = *(const uint2*)(pa + 24 * SAs + 16 * g);
        uint2 b0 = *(const uint2*)(pb + 16 * g);
        uint2 b1 = *(const uint2*)(pb + 8 * SBs + 16 * g);
        uint2 b2 = *(const uint2*)(pb + 16 * SBs + 16 * g);
        uint2 b3 = *(const uint2*)(pb + 24 * SBs + 16 * g);
        mma16(d[0][0], aA.x, aB.x, aA.y, aB.y, b0.x, b0.y);
        mma16(d[0][1], aA.x, aB.x, aA.y, aB.y, b1.x, b1.y);
        mma16(d[0][2], aA.x, aB.x, aA.y, aB.y, b2.x, b2.y);
        mma16(d[0][3], aA.x, aB.x, aA.y, aB.y, b3.x, b3.y);
        mma16(d[1][0], aC.x, aD.x, aC.y, aD.y, b0.x, b0.y);
        mma16(d[1][1], aC.x, aD.x, aC.y, aD.y, b1.x, b1.y);
        mma16(d[1][2], aC.x, aD.x, aC.y, aD.y, b2.x, b2.y);
        mma16(d[1][3], aC.x, aD.x, aC.y, aD.y, b3.x, b3.y);
    }
}

__device__ __forceinline__ void zero_acc(float (&d)[2][4][4]) {
#pragma unroll
    for (int i = 0; i < 2; i++)
#pragma unroll
        for (int j = 0; j < 4; j++)
#pragma unroll
            for (int k = 0; k < 4; k++) d[i][j][k] = 0.f;
}

// relu(d + bias) -> half into dst (k-storage layout), optional fp32 o store.
template <bool STORE_O>
__device__ __forceinline__ void epi_store(float (&d)[2][4][4], const float* __restrict__ bias,
                                          __half* __restrict__ dst, int SD,
                                          float* __restrict__ of,
                                          int wq, int wh, int r, int m) {
#pragma unroll
    for (int mt = 0; mt < 2; mt++) {
        int row0 = wq * 32 + mt * 16 + r;
#pragma unroll
        for (int nt = 0; nt < 4; nt++) {
            int c0 = wh * 32 + nt * 8 + 2 * m;
            float bv0 = bias[c0], bv1 = bias[c0 + 1];
            float x0 = fmaxf(d[mt][nt][0] + bv0, 0.f);
            float x1 = fmaxf(d[mt][nt][1] + bv1, 0.f);
            float x2 = fmaxf(d[mt][nt][2] + bv0, 0.f);
            float x3 = fmaxf(d[mt][nt][3] + bv1, 0.f);
            // half2 slot: k16-group g16 = wh*2 + nt/2, slot = 2m + (nt&1)
            int hoff = (wh * 2 + (nt >> 1)) * 16 + (2 * m + (nt & 1)) * 2;
            *reinterpret_cast<uint32_t*>(dst + row0 * SD + hoff) = h2(x0, x1);
            *reinterpret_cast<uint32_t*>(dst + (row0 + 8) * SD + hoff) = h2(x2, x3);
            if (STORE_O) {
                if (row0 < VROWS)
                    *reinterpret_cast<float2*>(of + row0 * SOF + c0) = make_float2(x0, x1);
                if (row0 + 8 < VROWS)
                    *reinterpret_cast<float2*>(of + (row0 + 8) * SOF + c0) = make_float2(x2, x3);
            }
        }
    }
}

// stage weight W[K][64] (gmem row-major) -> half dst[n][k-storage].
__device__ __forceinline__ void stage_wh(__half* __restrict__ dst, const float* __restrict__ W,
                                         int K, int strh, int tid) {
    for (int idx = tid; idx < K * 64; idx += TPB) {
        int k = idx >> 6, n = idx & 63;
        int gg = k >> 4, kr = k & 15, p = kr >> 1;
        int slot = (p & 3) * 2 + (p >> 2);
        dst[n * strh + gg * 16 + slot * 2 + (kr & 1)] = __float2half_rn(W[idx]);
    }
}

// write one row-segment of 64 source floats into k-storage half layout.
// dst = row base (halves), seg = which 64-col half (0/1).
__device__ __forceinline__ void pack_row64(__half* __restrict__ dst, const float* __restrict__ src,
                                           int seg) {
    __half* drow = dst + seg * 64;
#pragma unroll
    for (int gg = 0; gg < 4; gg++) {
        const float* s = src + gg * 16;
        float4 f0 = *(const float4*)(s + 0);
        float4 f1 = *(const float4*)(s + 4);
        float4 f2 = *(const float4*)(s + 8);
        float4 f3 = *(const float4*)(s + 12);
        uint32_t* d32 = reinterpret_cast<uint32_t*>(drow + gg * 16);
        // slot s holds pair p = (s&1)*4 + (s>>1): order p0,p4,p1,p5,p2,p6,p3,p7
        d32[0] = h2(f0.x, f0.y);   // p0
        d32[1] = h2(f2.x, f2.y);   // p4
        d32[2] = h2(f0.z, f0.w);   // p1
        d32[3] = h2(f2.z, f2.w);   // p5
        d32[4] = h2(f1.x, f1.y);   // p2
        d32[5] = h2(f3.x, f3.y);   // p6
        d32[6] = h2(f1.z, f1.w);   // p3
        d32[7] = h2(f3.z, f3.w);   // p7
    }
}

__global__ __launch_bounds__(TPB, 1)
void uv_agg_h(const int* __restrict__ nodes,
              const int* __restrict__ hist_uv,
              const int* __restrict__ hist_r,
              const float* __restrict__ v2e,
              const float* __restrict__ u2e,
              const float* __restrict__ r2e,
              const float* __restrict__ w1, const float* __restrict__ b1,
              const float* __restrict__ w2, const float* __restrict__ b2,
              const float* __restrict__ a1w, const float* __restrict__ a1b,
              const float* __restrict__ a2w, const float* __restrict__ a2b,
              const float* __restrict__ a3w, const float* __restrict__ a3b,
              float* __restrict__ out, int ngroups) {
    extern __shared__ char smem[];
    __half* hA0 = reinterpret_cast<__half*>(smem + O_A0);
    __half* hH  = reinterpret_cast<__half*>(smem + O_H);
    __half* hW1 = reinterpret_cast<__half*>(smem + O_W1);
    __half* hA1W = reinterpret_cast<__half*>(smem + O_A1W);
    __half* hW2 = reinterpret_cast<__half*>(smem + O_W2);
    __half* hA2W = reinterpret_cast<__half*>(smem + O_A2W);
    float* fOF  = reinterpret_cast<float*>(smem + O_OF);
    float* fB1  = reinterpret_cast<float*>(smem + O_B1);
    float* fB2  = reinterpret_cast<float*>(smem + O_B2);
    float* fAB1 = reinterpret_cast<float*>(smem + O_AB1);
    float* fAB2 = reinterpret_cast<float*>(smem + O_AB2);
    float* fA3  = reinterpret_cast<float*>(smem + O_A3);
    float* fUV  = reinterpret_cast<float*>(smem + O_UV);
    float* fLGP = reinterpret_cast<float*>(smem + O_LGP);
    float* fLG  = reinterpret_cast<float*>(smem + O_LG);

    const int tid = threadIdx.x;
    const int wid = tid >> 5, lane = tid & 31;
    const int wq = wid & 7;      // row octant (32 rows)
    const int wh = wid >> 3;     // col half (32 cols)
    const int r = lane >> 2, m = lane & 3;

    // ---- stage weights + biases once per CTA ----
    stage_wh(hW1, w1, 128, SA, tid);
    stage_wh(hA1W, a1w, 128, SA, tid);
    stage_wh(hW2, w2, 64, SH, tid);
    stage_wh(hA2W, a2w, 64, SH, tid);
    if (tid < 64) {
        fB1[tid]  = b1[tid];
        fB2[tid]  = b2[tid];
        fAB1[tid] = a1b[tid];
        fAB2[tid] = a2b[tid];
        fA3[tid]  = a3w[tid];
    }
    const float ab3v = a3b[0];
    __syncthreads();

    const int gr = tid >> 1, ghalf = tid & 1;     // gather: row 0..255, col-half
    const bool gvalid = gr < VROWS;
    const int gn = gvalid ? (gr / LHIST) : 0;
    const int gl = gr - gn * LHIST;

    for (int g = blockIdx.x; g < ngroups; g += gridDim.x) {
        const int b0 = g * NB;

        // ---- gather uv_rep + x = [e_uv|e_r] -> A0 ----
        if (tid < 256) {
            int n = tid >> 6, d = tid & 63;
            fUV[n * 64 + d] = u2e[(size_t)nodes[b0 + n] * 64 + d];
        }
        if (gvalid) {
            int hidx = (b0 + gn) * LHIST + gl;
            const float* src = ghalf ? (r2e + (size_t)hist_r[hidx] * 64)
                                     : (v2e + (size_t)hist_uv[hidx] * 64);
            // copy to registers then pack
            float buf[16];
            __half* drow = hA0 + gr * SA;
#pragma unroll
            for (int gg = 0; gg < 4; gg++) {
                float4 f0 = *(const float4*)(src + gg * 16 + 0);
                float4 f1 = *(const float4*)(src + gg * 16 + 4);
                float4 f2 = *(const float4*)(src + gg * 16 + 8);
                float4 f3 = *(const float4*)(src + gg * 16 + 12);
                uint32_t* d32 = reinterpret_cast<uint32_t*>(drow + ghalf * 64 + gg * 16);
                d32[0] = h2(f0.x, f0.y); d32[1] = h2(f2.x, f2.y);
                d32[2] = h2(f0.z, f0.w); d32[3] = h2(f2.z, f2.w);
                d32[4] = h2(f1.x, f1.y); d32[5] = h2(f3.x, f3.y);
                d32[6] = h2(f1.z, f1.w); d32[7] = h2(f3.z, f3.w);
            }
            (void)buf;
        }
        __syncthreads();

        float d[2][4][4];

        // ==== GEMM1: H = relu(X @ W1 + b1) ====
        zero_acc(d);
        gemm<8, SA, SA>(hA0, hW1, d, wq, wh, r, m);
        __syncthreads();                      // A0 reads done
        epi_store<false>(d, fB1, hH, SH, fOF, wq, wh, r, m);
        // uv_rep -> A0 cols 64..127
        if (gvalid) pack_row64(hA0 + gr * SA, fUV + gn * 64, 1);
        __syncthreads();                      // H + A0-uv ready

        // ==== GEMM2: o = relu(H @ W2 + b2) -> A0[0:64] half + OF fp32 ====
        zero_acc(d);
        gemm<4, SH, SH>(hH, hW2, d, wq, wh, r, m);
        epi_store<true>(d, fB2, hA0, SA, fOF, wq, wh, r, m);
        __syncthreads();                      // A0 [o|uv] ready

        // ==== GEMM3: H2 = relu([o|uv] @ A1w + ab1) ====
        zero_acc(d);
        gemm<8, SA, SA>(hA0, hA1W, d, wq, wh, r, m);
        epi_store<false>(d, fAB1, hH, SH, fOF, wq, wh, r, m);
        __syncthreads();                      // H2 ready

        // ==== GEMM4 + logit dot ====
        zero_acc(d);
        gemm<4, SH, SH>(hH, hA2W, d, wq, wh, r, m);
        {
            float p0[2] = {0.f, 0.f}, p1[2] = {0.f, 0.f};
#pragma unroll
            for (int mt = 0; mt < 2; mt++)
#pragma unroll
                for (int nt = 0; nt < 4; nt++) {
                    int c0 = wh * 32 + nt * 8 + 2 * m;
                    float w30 = fA3[c0], w31 = fA3[c0 + 1];
                    float bb0 = fAB2[c0], bb1 = fAB2[c0 + 1];
                    p0[mt] += fmaxf(d[mt][nt][0] + bb0, 0.f) * w30
                            + fmaxf(d[mt][nt][1] + bb1, 0.f) * w31;
                    p1[mt] += fmaxf(d[mt][nt][2] + bb0, 0.f) * w30
                            + fmaxf(d[mt][nt][3] + bb1, 0.f) * w31;
                }
#pragma unroll
            for (int off = 1; off <= 2; off <<= 1) {
#pragma unroll
                for (int mt = 0; mt < 2; mt++) {
                    p0[mt] += __shfl_xor_sync(0xffffffffu, p0[mt], off);
                    p1[mt] += __shfl_xor_sync(0xffffffffu, p1[mt], off);
                }
            }
            if (m == 0) {
#pragma unroll
                for (int mt = 0; mt < 2; mt++) {
                    int row = wq * 32 + mt * 16 + r;
                    fLGP[wh * 256 + row] = p0[mt];
                    fLGP[wh * 256 + row + 8] = p1[mt];
                }
            }
        }
        __syncthreads();
        if (tid < 256)
            fLG[tid] = fLGP[tid] + fLGP[256 + tid] + ab3v;
        __syncthreads();

        // ---- softmax(50) + weighted sum of o (fp32) ----
        if (tid < 256) {
            int n = tid >> 6, dcol = tid & 63;
            const float* lg = fLG + n * LHIST;
            const float* ob = fOF + n * LHIST * SOF + dcol;
            float mx = -1e30f;
#pragma unroll 10
            for (int l = 0; l < LHIST; l++) mx = fmaxf(mx, lg[l]);
            float s = 0.f, acc = 0.f;
#pragma unroll 10
            for (int l = 0; l < LHIST; l++) {
                float e = __expf(lg[l] - mx);
                s += e;
                acc += e * ob[l * SOF];
            }
            out[(size_t)(b0 + n) * 64 + dcol] = acc / s;
        }
        __syncthreads();   // protect LG/OF before next iteration's writers
    }
}

extern "C" void kernel_launch(void* const* d_in, const int* in_sizes, int n_in,
                              void* d_out, int out_size) {
    const int*   nodes = (const int*)d_in[0];
    const int*   huv   = (const int*)d_in[1];
    const int*   hr    = (const int*)d_in[2];
    const float* v2e   = (const float*)d_in[3];
    const float* u2e   = (const float*)d_in[4];
    const float* r2e   = (const float*)d_in[5];
    const float* w1    = (const float*)d_in[6];
    const float* b1    = (const float*)d_in[7];
    const float* w2    = (const float*)d_in[8];
    const float* b2    = (const float*)d_in[9];
    const float* a1w   = (const float*)d_in[10];
    const float* a1b   = (const float*)d_in[11];
    const float* a2w   = (const float*)d_in[12];
    const float* a2b   = (const float*)d_in[13];
    const float* a3w   = (const float*)d_in[14];
    const float* a3b   = (const float*)d_in[15];
    float* out = (float*)d_out;

    const int B = in_sizes[0];
    const int ngroups = B / NB;

    static int attr_set = 0;
    if (!attr_set) {
        cudaFuncSetAttribute(uv_agg_h, cudaFuncAttributeMaxDynamicSharedMemorySize, SMEM_BYTES);
        attr_set = 1;
    }
    uv_agg_h<<<148, TPB, SMEM_BYTES>>>(nodes, huv, hr, v2e, u2e, r2e,
                                       w1, b1, w2, b2, a1w, a1b, a2w, a2b,
                                       a3w, a3b, out, ngroups);
}

// round 5
// speedup vs baseline: 4.4703x; 1.1583x over previous
#include <cuda_runtime.h>
#include <cuda_fp16.h>
#include <cstdint>

// ============================================================================
// GraphRec UV_Aggregator — mma.sync m16n8k16 fp16 fused kernel, 2 CTAs/SM.
// compute_103-safe. 296 persistent CTAs x 256 threads (~107KB smem each).
// Per group: NB=2 nodes = 100 rows -> 128x64 tile:
//   GEMM1(K=128) -> GEMM2(K=64) -> ATT1(K=64, uv folded into bias via uvatt)
//   -> ATT2(K=64) -> logits -> softmax(50) -> weighted sum (o read as fp16).
// Operands fp16 pair-permuted so every fragment is one 8B LDS.64.
// ============================================================================

#define TPB   256
#define NB    2
#define LHIST 50
#define VROWS 100
#define SA    136    // halves stride, 128-k buffers
#define SH    72     // halves stride, 64-k buffers

// ---- smem byte offsets ----
#define O_A0   0u        // 128 x SA halves : X, later o in cols 0..63
#define O_H    34816u    // 128 x SH halves : hidden / H2
#define O_W1   53248u    // 64 x SA halves
#define O_A1W  70656u    // 64 x SA halves (A1_top in k 0..63, A1_bot in k 64..127)
#define O_W2   88064u    // 64 x SH halves
#define O_A2W  97280u
#define O_B1   106496u
#define O_B2   106752u
#define O_AB1  107008u
#define O_AB2  107264u
#define O_A3   107520u
#define O_UV   107776u   // 2 x 64 fp32
#define O_UVA  108288u   // 2 x 64 fp32 : uv @ A1_bot
#define O_LGP  108800u   // 2 x 128 fp32 logit partials
#define SMEM_BYTES 109824u

__device__ __forceinline__ void mma16(float (&d)[4], uint32_t a0, uint32_t a1,
                                      uint32_t a2, uint32_t a3, uint32_t b0, uint32_t b1) {
    asm volatile(
        "mma.sync.aligned.m16n8k16.row.col.f32.f16.f16.f32 "
        "{%0,%1,%2,%3}, {%4,%5,%6,%7}, {%8,%9}, {%0,%1,%2,%3};"
        : "+f"(d[0]), "+f"(d[1]), "+f"(d[2]), "+f"(d[3])
        : "r"(a0), "r"(a1), "r"(a2), "r"(a3), "r"(b0), "r"(b1));
}

__device__ __forceinline__ uint32_t h2(float lo, float hi) {
    __half2 h = __floats2half2_rn(lo, hi);
    return *reinterpret_cast<uint32_t*>(&h);
}

// fp16 storage index of logical col c within a row (pair-permuted k16 groups)
__device__ __forceinline__ int offcol(int c) {
    int gg = c >> 4, kr = c & 15, p = kr >> 1;
    int slot = (p & 3) * 2 + (p >> 2);
    return gg * 16 + slot * 2 + (kr & 1);
}

// GEMM: C[2 m16][4 n8] += A(rows 32wq..+31) @ B(cols 32wh..+31)^T
template <int KST, int SAs, int SBs>
__device__ __forceinline__ void gemm(const __half* __restrict__ As,
                                     const __half* __restrict__ Bs,
                                     float (&d)[2][4][4],
                                     int wq, int wh, int r, int m) {
    const __half* pa = As + (wq * 32 + r) * SAs + m * 4;
    const __half* pb = Bs + (wh * 32 + r) * SBs + m * 4;
#pragma unroll
    for (int g = 0; g < KST; g++) {
        uint2 aA = *(const uint2*)(pa + 16 * g);
        uint2 aB = *(const uint2*)(pa + 8 * SAs + 16 * g);
        uint2 aC = *(const uint2*)(pa + 16 * SAs + 16 * g);
        uint2 aD = *(const uint2*)(pa + 24 * SAs + 16 * g);
        uint2 b0 = *(const uint2*)(pb + 16 * g);
        uint2 b1 = *(const uint2*)(pb + 8 * SBs + 16 * g);
        uint2 b2 = *(const uint2*)(pb + 16 * SBs + 16 * g);
        uint2 b3 = *(const uint2*)(pb + 24 * SBs + 16 * g);
        mma16(d[0][0], aA.x, aB.x, aA.y, aB.y, b0.x, b0.y);
        mma16(d[0][1], aA.x, aB.x, aA.y, aB.y, b1.x, b1.y);
        mma16(d[0][2], aA.x, aB.x, aA.y, aB.y, b2.x, b2.y);
        mma16(d[0][3], aA.x, aB.x, aA.y, aB.y, b3.x, b3.y);
        mma16(d[1][0], aC.x, aD.x, aC.y, aD.y, b0.x, b0.y);
        mma16(d[1][1], aC.x, aD.x, aC.y, aD.y, b1.x, b1.y);
        mma16(d[1][2], aC.x, aD.x, aC.y, aD.y, b2.x, b2.y);
        mma16(d[1][3], aC.x, aD.x, aC.y, aD.y, b3.x, b3.y);
    }
}

__device__ __forceinline__ void zero_acc(float (&d)[2][4][4]) {
#pragma unroll
    for (int i = 0; i < 2; i++)
#pragma unroll
        for (int j = 0; j < 4; j++)
#pragma unroll
            for (int k = 0; k < 4; k++) d[i][j][k] = 0.f;
}

// relu(d + bias) -> half k-storage
template <int SD>
__device__ __forceinline__ void epi_store(float (&d)[2][4][4], const float* __restrict__ bias,
                                          __half* __restrict__ dst,
                                          int wq, int wh, int r, int m) {
#pragma unroll
    for (int mt = 0; mt < 2; mt++) {
        int row0 = wq * 32 + mt * 16 + r;
#pragma unroll
        for (int nt = 0; nt < 4; nt++) {
            int c0 = wh * 32 + nt * 8 + 2 * m;
            float bv0 = bias[c0], bv1 = bias[c0 + 1];
            int hoff = (wh * 2 + (nt >> 1)) * 16 + (2 * m + (nt & 1)) * 2;
            *reinterpret_cast<uint32_t*>(dst + row0 * SD + hoff) =
                h2(fmaxf(d[mt][nt][0] + bv0, 0.f), fmaxf(d[mt][nt][1] + bv1, 0.f));
            *reinterpret_cast<uint32_t*>(dst + (row0 + 8) * SD + hoff) =
                h2(fmaxf(d[mt][nt][2] + bv0, 0.f), fmaxf(d[mt][nt][3] + bv1, 0.f));
        }
    }
}

// epi3: relu(d + ab1 + uvatt[node(row)]) -> half k-storage
__device__ __forceinline__ void epi3(float (&d)[2][4][4], const float* __restrict__ bias,
                                     const float* __restrict__ uva,
                                     __half* __restrict__ dst,
                                     int wq, int wh, int r, int m) {
#pragma unroll
    for (int mt = 0; mt < 2; mt++) {
        int row0 = wq * 32 + mt * 16 + r;
        int na = (row0 >= LHIST) ? 1 : 0;
        int nb = (row0 + 8 >= LHIST) ? 1 : 0;
#pragma unroll
        for (int nt = 0; nt < 4; nt++) {
            int c0 = wh * 32 + nt * 8 + 2 * m;
            float bv0 = bias[c0], bv1 = bias[c0 + 1];
            float ua0 = uva[na * 64 + c0], ua1 = uva[na * 64 + c0 + 1];
            float ub0 = uva[nb * 64 + c0], ub1 = uva[nb * 64 + c0 + 1];
            int hoff = (wh * 2 + (nt >> 1)) * 16 + (2 * m + (nt & 1)) * 2;
            *reinterpret_cast<uint32_t*>(dst + row0 * SH + hoff) =
                h2(fmaxf(d[mt][nt][0] + bv0 + ua0, 0.f), fmaxf(d[mt][nt][1] + bv1 + ua1, 0.f));
            *reinterpret_cast<uint32_t*>(dst + (row0 + 8) * SH + hoff) =
                h2(fmaxf(d[mt][nt][2] + bv0 + ub0, 0.f), fmaxf(d[mt][nt][3] + bv1 + ub1, 0.f));
        }
    }
}

// stage weight W[K][64] (gmem row-major) -> half dst[n][k-storage].
__device__ __forceinline__ void stage_wh(__half* __restrict__ dst, const float* __restrict__ W,
                                         int K, int strh, int tid) {
    for (int idx = tid; idx < K * 64; idx += TPB) {
        int k = idx >> 6, n = idx & 63;
        dst[n * strh + offcol(k)] = __float2half_rn(W[idx]);
    }
}

__global__ __launch_bounds__(TPB, 2)
void uv_agg_h2(const int* __restrict__ nodes,
               const int* __restrict__ hist_uv,
               const int* __restrict__ hist_r,
               const float* __restrict__ v2e,
               const float* __restrict__ u2e,
               const float* __restrict__ r2e,
               const float* __restrict__ w1, const float* __restrict__ b1,
               const float* __restrict__ w2, const float* __restrict__ b2,
               const float* __restrict__ a1w, const float* __restrict__ a1b,
               const float* __restrict__ a2w, const float* __restrict__ a2b,
               const float* __restrict__ a3w, const float* __restrict__ a3b,
               float* __restrict__ out, int ngroups) {
    extern __shared__ char smem[];
    __half* hA0  = reinterpret_cast<__half*>(smem + O_A0);
    __half* hH   = reinterpret_cast<__half*>(smem + O_H);
    __half* hW1  = reinterpret_cast<__half*>(smem + O_W1);
    __half* hA1W = reinterpret_cast<__half*>(smem + O_A1W);
    __half* hW2  = reinterpret_cast<__half*>(smem + O_W2);
    __half* hA2W = reinterpret_cast<__half*>(smem + O_A2W);
    float* fB1  = reinterpret_cast<float*>(smem + O_B1);
    float* fB2  = reinterpret_cast<float*>(smem + O_B2);
    float* fAB1 = reinterpret_cast<float*>(smem + O_AB1);
    float* fAB2 = reinterpret_cast<float*>(smem + O_AB2);
    float* fA3  = reinterpret_cast<float*>(smem + O_A3);
    float* fUV  = reinterpret_cast<float*>(smem + O_UV);
    float* fUVA = reinterpret_cast<float*>(smem + O_UVA);
    float* fLGP = reinterpret_cast<float*>(smem + O_LGP);

    const int tid = threadIdx.x;
    const int wid = tid >> 5, lane = tid & 31;
    const int wq = wid & 3;      // row octant (32 rows of 128)
    const int wh = wid >> 2;     // col half (32 cols of 64)
    const int r = lane >> 2, m = lane & 3;

    // ---- stage weights + biases once per CTA ----
    stage_wh(hW1, w1, 128, SA, tid);
    stage_wh(hA1W, a1w, 128, SA, tid);   // top 64 k = A1_top, k 64..127 = A1_bot
    stage_wh(hW2, w2, 64, SH, tid);
    stage_wh(hA2W, a2w, 64, SH, tid);
    if (tid < 64) {
        fB1[tid]  = b1[tid];
        fB2[tid]  = b2[tid];
        fAB1[tid] = a1b[tid];
        fAB2[tid] = a2b[tid];
        fA3[tid]  = a3w[tid];
    }
    const float ab3v = a3b[0];
    __syncthreads();

    const int gr = tid >> 1, ghalf = tid & 1;   // gather: row 0..127, col-half
    const bool gvalid = gr < VROWS;
    const int gn = (gr >= LHIST) ? 1 : 0;
    const int gl = gr - gn * LHIST;

    const int sn = tid >> 6;            // softmax: node (tid<128)
    const int sd = tid & 63;            // softmax: dim
    const int sdo = offcol(sd);

    for (int g = blockIdx.x; g < ngroups; g += gridDim.x) {
        const int b0 = g * NB;

        // ---- gather uv_rep + X = [e_uv|e_r] -> A0 ----
        if (tid < 128) {
            int n = tid >> 6, d2 = tid & 63;
            fUV[n * 64 + d2] = u2e[(size_t)nodes[b0 + n] * 64 + d2];
        }
        if (gvalid) {
            int hidx = (b0 + gn) * LHIST + gl;
            const float* src = ghalf ? (r2e + (size_t)hist_r[hidx] * 64)
                                     : (v2e + (size_t)hist_uv[hidx] * 64);
            __half* drow = hA0 + gr * SA + ghalf * 64;
#pragma unroll
            for (int gg = 0; gg < 4; gg++) {
                float4 f0 = *(const float4*)(src + gg * 16 + 0);
                float4 f1 = *(const float4*)(src + gg * 16 + 4);
                float4 f2 = *(const float4*)(src + gg * 16 + 8);
                float4 f3 = *(const float4*)(src + gg * 16 + 12);
                uint32_t* d32 = reinterpret_cast<uint32_t*>(drow + gg * 16);
                d32[0] = h2(f0.x, f0.y); d32[1] = h2(f2.x, f2.y);
                d32[2] = h2(f0.z, f0.w); d32[3] = h2(f2.z, f2.w);
                d32[4] = h2(f1.x, f1.y); d32[5] = h2(f3.x, f3.y);
                d32[6] = h2(f1.z, f1.w); d32[7] = h2(f3.z, f3.w);
            }
        }
        __syncthreads();                               // (1) X + fUV ready

        // ---- uvatt[n][c] = uv[n] . A1_bot[:,c]  (fp32 acc, fp16 weights) ----
        if (tid < 128) {
            int n = tid >> 6, c = tid & 63;
            const float* uvp = fUV + n * 64;
            const __half2* w = reinterpret_cast<const __half2*>(hA1W + c * SA + 64);
            float acc = 0.f;
#pragma unroll
            for (int gg = 0; gg < 4; gg++) {
                int jb = gg * 16;
                const __half2* wg = w + gg * 8;
                float2 q;
                q = __half22float2(wg[0]); acc += q.x * uvp[jb + 0] + q.y * uvp[jb + 1];
                q = __half22float2(wg[1]); acc += q.x * uvp[jb + 8] + q.y * uvp[jb + 9];
                q = __half22float2(wg[2]); acc += q.x * uvp[jb + 2] + q.y * uvp[jb + 3];
                q = __half22float2(wg[3]); acc += q.x * uvp[jb + 10] + q.y * uvp[jb + 11];
                q = __half22float2(wg[4]); acc += q.x * uvp[jb + 4] + q.y * uvp[jb + 5];
                q = __half22float2(wg[5]); acc += q.x * uvp[jb + 12] + q.y * uvp[jb + 13];
                q = __half22float2(wg[6]); acc += q.x * uvp[jb + 6] + q.y * uvp[jb + 7];
                q = __half22float2(wg[7]); acc += q.x * uvp[jb + 14] + q.y * uvp[jb + 15];
            }
            fUVA[n * 64 + c] = acc;
        }

        float d[2][4][4];

        // ==== GEMM1: H = relu(X @ W1 + b1) -> hH ====
        zero_acc(d);
        gemm<8, SA, SA>(hA0, hW1, d, wq, wh, r, m);
        epi_store<SH>(d, fB1, hH, wq, wh, r, m);
        __syncthreads();                               // (2) H + uvatt ready

        // ==== GEMM2: o = relu(H @ W2 + b2) -> hA0 cols 0..63 ====
        zero_acc(d);
        gemm<4, SH, SH>(hH, hW2, d, wq, wh, r, m);
        epi_store<SA>(d, fB2, hA0, wq, wh, r, m);
        __syncthreads();                               // (3) o ready

        // ==== GEMM3: H2 = relu(o @ A1_top + ab1 + uvatt[n]) -> hH ====
        zero_acc(d);
        gemm<4, SA, SA>(hA0, hA1W, d, wq, wh, r, m);
        epi3(d, fAB1, fUVA, hH, wq, wh, r, m);
        __syncthreads();                               // (4) H2 ready

        // ==== GEMM4 + logit partial dot ====
        zero_acc(d);
        gemm<4, SH, SH>(hH, hA2W, d, wq, wh, r, m);
        {
            float p0[2] = {0.f, 0.f}, p1[2] = {0.f, 0.f};
#pragma unroll
            for (int mt = 0; mt < 2; mt++)
#pragma unroll
                for (int nt = 0; nt < 4; nt++) {
                    int c0 = wh * 32 + nt * 8 + 2 * m;
                    float w30 = fA3[c0], w31 = fA3[c0 + 1];
                    float bb0 = fAB2[c0], bb1 = fAB2[c0 + 1];
                    p0[mt] += fmaxf(d[mt][nt][0] + bb0, 0.f) * w30
                            + fmaxf(d[mt][nt][1] + bb1, 0.f) * w31;
                    p1[mt] += fmaxf(d[mt][nt][2] + bb0, 0.f) * w30
                            + fmaxf(d[mt][nt][3] + bb1, 0.f) * w31;
                }
#pragma unroll
            for (int off = 1; off <= 2; off <<= 1) {
#pragma unroll
                for (int mt = 0; mt < 2; mt++) {
                    p0[mt] += __shfl_xor_sync(0xffffffffu, p0[mt], off);
                    p1[mt] += __shfl_xor_sync(0xffffffffu, p1[mt], off);
                }
            }
            if (m == 0) {
#pragma unroll
                for (int mt = 0; mt < 2; mt++) {
                    int row = wq * 32 + mt * 16 + r;
                    fLGP[wh * 128 + row] = p0[mt];
                    fLGP[wh * 128 + row + 8] = p1[mt];
                }
            }
        }
        __syncthreads();                               // (5) logit partials ready

        // ---- softmax(50) + weighted sum of o (fp16 from A0) ----
        if (tid < 128) {
            const float* lgA = fLGP + sn * LHIST;
            const float* lgB = fLGP + 128 + sn * LHIST;
            const __half* ob = hA0 + sn * LHIST * SA + sdo;
            float mx = -1e30f;
#pragma unroll 10
            for (int l = 0; l < LHIST; l++) mx = fmaxf(mx, lgA[l] + lgB[l]);
            float s = 0.f, acc = 0.f;
#pragma unroll 10
            for (int l = 0; l < LHIST; l++) {
                float e = __expf(lgA[l] + lgB[l] - mx);
                s += e;
                acc += e * __half2float(ob[l * SA]);
            }
            out[(size_t)(b0 + sn) * 64 + sd] = acc / s;
        }
        __syncthreads();                               // (6) protect A0/LGP/UV
    }
    (void)ab3v;   // constant bias cancels in softmax; kept for clarity
}

extern "C" void kernel_launch(void* const* d_in, const int* in_sizes, int n_in,
                              void* d_out, int out_size) {
    const int*   nodes = (const int*)d_in[0];
    const int*   huv   = (const int*)d_in[1];
    const int*   hr    = (const int*)d_in[2];
    const float* v2e   = (const float*)d_in[3];
    const float* u2e   = (const float*)d_in[4];
    const float* r2e   = (const float*)d_in[5];
    const float* w1    = (const float*)d_in[6];
    const float* b1    = (const float*)d_in[7];
    const float* w2    = (const float*)d_in[8];
    const float* b2    = (const float*)d_in[9];
    const float* a1w   = (const float*)d_in[10];
    const float* a1b   = (const float*)d_in[11];
    const float* a2w   = (const float*)d_in[12];
    const float* a2b   = (const float*)d_in[13];
    const float* a3w   = (const float*)d_in[14];
    const float* a3b   = (const float*)d_in[15];
    float* out = (float*)d_out;

    const int B = in_sizes[0];
    const int ngroups = B / NB;

    static int attr_set = 0;
    if (!attr_set) {
        cudaFuncSetAttribute(uv_agg_h2, cudaFuncAttributeMaxDynamicSharedMemorySize, SMEM_BYTES);
        attr_set = 1;
    }
    uv_agg_h2<<<296, TPB, SMEM_BYTES>>>(nodes, huv, hr, v2e, u2e, r2e,
                                        w1, b1, w2, b2, a1w, a1b, a2w, a2b,
                                        a3w, a3b, out, ngroups);
}